// round 10
// baseline (speedup 1.0000x reference)
#include <cuda_runtime.h>
#include <math.h>
#include <stdint.h>

#define NTOK 4096
#define DM   1024
#define DFF  2816
#define NEXP 8
#define NSEG 9
#define SEG  4096
#define KC   64              // K elements per SMEM chunk (2 imma k-steps)

#define PLANE  10240         // 128 rows * 80 bytes (64 s8 + 16 pad)
#define STAGEB (4 * PLANE)   // Aq1, Aq2, Bq1, Bq2
#define NSTAGE 3
#define SMEM_TOTAL (2048 + NSTAGE * STAGEB)   // 124928

// ---------------- scratch (device globals; allocation-free) ----------------
__device__ int     g_cnt[NEXP];
__device__ int     g_rows[NEXP * SEG];
__device__ float   g_rw[NSEG * SEG];
__device__ int     g_pos[NTOK * 2];
// quantized activations
__device__ int8_t  g_xq1[(size_t)NTOK * DM];
__device__ int8_t  g_xq2[(size_t)NTOK * DM];
__device__ float   g_xs[NTOK];
// quantized weights (2 limbs + per-row scale)
__device__ int8_t  g_w1q1[(size_t)NEXP * DFF * DM];
__device__ int8_t  g_w1q2[(size_t)NEXP * DFF * DM];
__device__ float   g_w1s[NEXP * DFF];
__device__ int8_t  g_w3q1[(size_t)NEXP * DFF * DM];
__device__ int8_t  g_w3q2[(size_t)NEXP * DFF * DM];
__device__ float   g_w3s[NEXP * DFF];
__device__ int8_t  g_w2q1[(size_t)NEXP * DM * DFF];
__device__ int8_t  g_w2q2[(size_t)NEXP * DM * DFF];
__device__ float   g_w2s[NEXP * DM];
__device__ int8_t  g_s1q1[(size_t)DFF * DM];
__device__ int8_t  g_s1q2[(size_t)DFF * DM];
__device__ float   g_s1s[DFF];
__device__ int8_t  g_s3q1[(size_t)DFF * DM];
__device__ int8_t  g_s3q2[(size_t)DFF * DM];
__device__ float   g_s3s[DFF];
__device__ int8_t  g_s2q1[(size_t)DM * DFF];
__device__ int8_t  g_s2q2[(size_t)DM * DFF];
__device__ float   g_s2s[DM];
// intermediates
__device__ float   g_h1[(size_t)NSEG * SEG * DFF];   // up1 (pre-activation)
__device__ float   g_hp[(size_t)NSEG * SEG * DFF];   // gelu(h1)*h3 fp32
__device__ int8_t  g_hq1[(size_t)NSEG * SEG * DFF];
__device__ int8_t  g_hq2[(size_t)NSEG * SEG * DFF];
__device__ float   g_hs[NSEG * SEG];
__device__ float   g_orow[(size_t)NSEG * SEG * DM];

// ---------------- helpers ----------------
__device__ __forceinline__ uint32_t smem_u32(const void* p) {
    uint32_t a;
    asm("{ .reg .u64 t; cvta.to.shared.u64 t, %1; cvt.u32.u64 %0, t; }" : "=r"(a) : "l"(p));
    return a;
}
#define CP_ASYNC16(dst, src) \
    asm volatile("cp.async.cg.shared.global [%0], [%1], 16;" :: "r"(dst), "l"(src))
#define CP_COMMIT()  asm volatile("cp.async.commit_group;" ::: "memory")
#define CP_WAIT2()   asm volatile("cp.async.wait_group 2;" ::: "memory")

__device__ __forceinline__ void imma16832(int* d, const uint32_t* a, const uint32_t* b) {
    asm volatile(
        "mma.sync.aligned.m16n8k32.row.col.s32.s8.s8.s32 "
        "{%0,%1,%2,%3}, {%4,%5,%6,%7}, {%8,%9}, {%0,%1,%2,%3};"
        : "+r"(d[0]), "+r"(d[1]), "+r"(d[2]), "+r"(d[3])
        : "r"(a[0]), "r"(a[1]), "r"(a[2]), "r"(a[3]), "r"(b[0]), "r"(b[1]));
}
__device__ __forceinline__ int8_t q_clamp(float v) {
    float c = fminf(fmaxf(v, -127.f), 127.f);
    return (int8_t)(int)c;
}

// ---------------- prep: reset counters + quantize all 6 weight tensors ----------------
// One block per weight row. Ranges: w1(22528,K=1024) w3(22528) w2(8192,K=2816)
//                                   sw1(2816) sw3(2816) sw2(1024,K=2816)
__global__ void k_prep(const float* __restrict__ w1, const float* __restrict__ w2,
                       const float* __restrict__ w3, const float* __restrict__ s1,
                       const float* __restrict__ s2, const float* __restrict__ s3) {
    __shared__ float red[8];
    __shared__ float s_max;
    int b = blockIdx.x, tid = threadIdx.x;
    if (b == 0 && tid < NEXP) g_cnt[tid] = 0;

    const float* src;
    int8_t *q1, *q2;
    float* sc;
    int K, row;
    if (b < 22528)      { row = b;          K = DM;  src = w1; q1 = g_w1q1; q2 = g_w1q2; sc = g_w1s; }
    else if (b < 45056) { row = b - 22528;  K = DM;  src = w3; q1 = g_w3q1; q2 = g_w3q2; sc = g_w3s; }
    else if (b < 53248) { row = b - 45056;  K = DFF; src = w2; q1 = g_w2q1; q2 = g_w2q2; sc = g_w2s; }
    else if (b < 56064) { row = b - 53248;  K = DM;  src = s1; q1 = g_s1q1; q2 = g_s1q2; sc = g_s1s; }
    else if (b < 58880) { row = b - 56064;  K = DM;  src = s3; q1 = g_s3q1; q2 = g_s3q2; sc = g_s3s; }
    else                { row = b - 58880;  K = DFF; src = s2; q1 = g_s2q1; q2 = g_s2q2; sc = g_s2s; }

    const float* r = src + (size_t)row * K;
    float m = 0.f;
    for (int i = tid; i < K; i += 256) m = fmaxf(m, fabsf(r[i]));
#pragma unroll
    for (int o = 16; o; o >>= 1) m = fmaxf(m, __shfl_xor_sync(0xffffffffu, m, o));
    if ((tid & 31) == 0) red[tid >> 5] = m;
    __syncthreads();
    if (tid == 0) {
        float mm = 0.f;
#pragma unroll
        for (int i = 0; i < 8; i++) mm = fmaxf(mm, red[i]);
        s_max = mm;
    }
    __syncthreads();
    float mx = s_max;
    float s = mx * (1.f / 127.f);
    float inv1 = (mx > 0.f) ? 127.f / mx : 0.f;
    size_t base = (size_t)row * K;
    for (int i = tid; i < K; i += 256) {
        float a = r[i];
        float q1f = rintf(a * inv1);
        q1f = fminf(fmaxf(q1f, -127.f), 127.f);
        float rr = a - q1f * s;
        q1[base + i] = (int8_t)(int)q1f;
        q2[base + i] = q_clamp(rintf(rr * inv1 * 256.f));
    }
    if (tid == 0) sc[row] = s;
}

// ---------------- RMSNorm + gating + routing + x_norm quantization ----------------
__global__ void k_rms_gate(const float* __restrict__ x, const float* __restrict__ gw) {
    __shared__ float xs[DM];
    __shared__ float red[8];
    __shared__ float logits[NEXP];
    __shared__ float s_scale;
    __shared__ float s_max;

    int t = blockIdx.x, tid = threadIdx.x;
    const float* xr = x + (size_t)t * DM;

    float v[4];
    float ss = 0.f;
#pragma unroll
    for (int i = 0; i < 4; i++) { v[i] = xr[tid + 256 * i]; ss += v[i] * v[i]; }
#pragma unroll
    for (int o = 16; o; o >>= 1) ss += __shfl_xor_sync(0xffffffffu, ss, o);
    if ((tid & 31) == 0) red[tid >> 5] = ss;
    __syncthreads();
    if (tid == 0) {
        float s = 0.f;
#pragma unroll
        for (int i = 0; i < 8; i++) s += red[i];
        s_scale = rsqrtf(s / (float)DM + 1e-6f);
    }
    __syncthreads();
    float sc = s_scale;
    float y[4];
    float m = 0.f;
#pragma unroll
    for (int i = 0; i < 4; i++) {
        y[i] = v[i] * sc;
        xs[tid + 256 * i] = y[i];
        m = fmaxf(m, fabsf(y[i]));
    }
    __syncthreads();

    // row max for quantization
#pragma unroll
    for (int o = 16; o; o >>= 1) m = fmaxf(m, __shfl_xor_sync(0xffffffffu, m, o));
    if ((tid & 31) == 0) red[tid >> 5] = m;
    __syncthreads();
    if (tid == 0) {
        float mm = 0.f;
#pragma unroll
        for (int i = 0; i < 8; i++) mm = fmaxf(mm, red[i]);
        s_max = mm;
        g_xs[t] = mm * (1.f / 127.f);
    }
    __syncthreads();
    float mx = s_max;
    float qs = mx * (1.f / 127.f);
    float inv1 = (mx > 0.f) ? 127.f / mx : 0.f;
#pragma unroll
    for (int i = 0; i < 4; i++) {
        size_t idx = (size_t)t * DM + tid + 256 * i;
        float q1f = rintf(y[i] * inv1);
        q1f = fminf(fmaxf(q1f, -127.f), 127.f);
        float rr = y[i] - q1f * qs;
        g_xq1[idx] = (int8_t)(int)q1f;
        g_xq2[idx] = q_clamp(rintf(rr * inv1 * 256.f));
    }

    int w = tid >> 5, lane = tid & 31;
    const float* ge = gw + w * DM;
    float acc = 0.f;
    for (int i = lane; i < DM; i += 32) acc += xs[i] * ge[i];
#pragma unroll
    for (int o = 16; o; o >>= 1) acc += __shfl_xor_sync(0xffffffffu, acc, o);
    if (lane == 0) logits[w] = acc;
    __syncthreads();

    if (tid == 0) {
        int b0 = 0; float l0 = logits[0];
        for (int e = 1; e < NEXP; e++) if (logits[e] > l0) { l0 = logits[e]; b0 = e; }
        int b1 = -1; float l1 = -1e30f;
        for (int e = 0; e < NEXP; e++) if (e != b0 && logits[e] > l1) { l1 = logits[e]; b1 = e; }
        float w0 = 1.f / (1.f + expf(l1 - l0));
        float w1v = 1.f - w0;
        int s0 = atomicAdd(&g_cnt[b0], 1);
        g_rows[b0 * SEG + s0] = t; g_rw[b0 * SEG + s0] = w0;  g_pos[t * 2 + 0] = b0 * SEG + s0;
        int s1 = atomicAdd(&g_cnt[b1], 1);
        g_rows[b1 * SEG + s1] = t; g_rw[b1 * SEG + s1] = w1v; g_pos[t * 2 + 1] = b1 * SEG + s1;
    }
}

// ---------------- stage loader: pure cp.async of s8 limb planes ----------------
// planes: 0=Aq1 1=Aq2 2=Bq1 3=Bq2; each 128 rows x 64 s8, 80B row stride.
template <int MODE, int K>
__device__ __forceinline__ void load_stage(uint32_t sbase, int stg, const int* rowtok,
                                           int e, int cnt, int m0, int n0,
                                           const int8_t* Aq1, const int8_t* Aq2,
                                           const int8_t* Bq1, const int8_t* Bq2,
                                           int kc, int tid) {
    uint32_t stbase = sbase + 2048 + stg * STAGEB;
#pragma unroll
    for (int c = 0; c < 8; c++) {
        int i = tid + c * 256;        // 0..2047
        int plane = i >> 9;
        int j = i & 511;
        int row = j >> 2;
        int kq = (j & 3) * 16;        // byte offset within 64B row chunk
        const int8_t* src;
        if (plane < 2) {
            const int8_t* P = plane ? Aq2 : Aq1;
            size_t r;
            if (MODE < 2) {
                r = (size_t)rowtok[row];
            } else {
                int rr = m0 + row;
                if (rr >= cnt) rr = m0;
                r = (size_t)e * SEG + rr;
            }
            src = P + r * K + kc * KC + kq;
        } else {
            const int8_t* P = (plane == 2) ? Bq1 : Bq2;
            src = P + (size_t)(n0 + row) * K + kc * KC + kq;
        }
        uint32_t dst = stbase + plane * PLANE + row * 80 + (j & 3) * 16;
        CP_ASYNC16(dst, src);
    }
}

// ---------------- per-stage compute: 2 x k32 imma steps, 3-term limb split ----------------
__device__ __forceinline__ void compute_stage(const char* st, int accH[2][8][4],
                                              int accM[2][8][4], int lane, int wm, int wn) {
    int g = lane >> 2, tg = lane & 3;
    const char* A1 = st;
    const char* A2 = st + PLANE;
    const char* B1p = st + 2 * PLANE;
    const char* B2p = st + 3 * PLANE;
#pragma unroll
    for (int ks = 0; ks < 2; ks++) {
        int koff = ks * 32 + tg * 4;
        uint32_t a1[2][4], a2[2][4];
#pragma unroll
        for (int mt = 0; mt < 2; mt++) {
            int rb = wm * 32 + mt * 16;
            a1[mt][0] = *(const uint32_t*)(A1 + (rb + g) * 80 + koff);
            a1[mt][1] = *(const uint32_t*)(A1 + (rb + g + 8) * 80 + koff);
            a1[mt][2] = *(const uint32_t*)(A1 + (rb + g) * 80 + koff + 16);
            a1[mt][3] = *(const uint32_t*)(A1 + (rb + g + 8) * 80 + koff + 16);
            a2[mt][0] = *(const uint32_t*)(A2 + (rb + g) * 80 + koff);
            a2[mt][1] = *(const uint32_t*)(A2 + (rb + g + 8) * 80 + koff);
            a2[mt][2] = *(const uint32_t*)(A2 + (rb + g) * 80 + koff + 16);
            a2[mt][3] = *(const uint32_t*)(A2 + (rb + g + 8) * 80 + koff + 16);
        }
#pragma unroll
        for (int nt = 0; nt < 8; nt++) {
            int nr = wn * 64 + nt * 8 + g;
            uint32_t b1[2], b2[2];
            b1[0] = *(const uint32_t*)(B1p + nr * 80 + koff);
            b1[1] = *(const uint32_t*)(B1p + nr * 80 + koff + 16);
            b2[0] = *(const uint32_t*)(B2p + nr * 80 + koff);
            b2[1] = *(const uint32_t*)(B2p + nr * 80 + koff + 16);
#pragma unroll
            for (int mt = 0; mt < 2; mt++) {
                imma16832(accH[mt][nt], a1[mt], b1);
                imma16832(accM[mt][nt], a1[mt], b2);
                imma16832(accM[mt][nt], a2[mt], b1);
            }
        }
    }
}

// ---------------- IMMA GEMM, 3-stage cp.async pipeline ----------------
// MODE 0: up1 (A = gathered x quant, B = w1) -> g_h1 fp32
// MODE 1: up3 (A = gathered x quant, B = w3) -> epi: gelu(g_h1)*d -> g_hp fp32
// MODE 2: down (A = h quant,        B = w2) -> g_orow fp32
template <int MODE>
__global__ __launch_bounds__(256, 1)
void k_gemm() {
    constexpr int K    = (MODE < 2) ? DM : DFF;
    constexpr int NOUT = (MODE < 2) ? DFF : DM;
    constexpr int NC   = K / KC;

    extern __shared__ char smem[];
    int e = blockIdx.z;
    int cnt = (e == 8) ? SEG : g_cnt[e];
    int m0 = blockIdx.y * 128;
    if (m0 >= cnt) return;
    int n0 = blockIdx.x * 128;

    const int8_t *Aq1, *Aq2, *Bq1, *Bq2;
    const float* Bs;
    if (MODE == 0) {
        Bq1 = (e == 8) ? g_s1q1 : g_w1q1 + (size_t)e * NOUT * K;
        Bq2 = (e == 8) ? g_s1q2 : g_w1q2 + (size_t)e * NOUT * K;
        Bs  = (e == 8) ? g_s1s  : g_w1s + e * NOUT;
    } else if (MODE == 1) {
        Bq1 = (e == 8) ? g_s3q1 : g_w3q1 + (size_t)e * NOUT * K;
        Bq2 = (e == 8) ? g_s3q2 : g_w3q2 + (size_t)e * NOUT * K;
        Bs  = (e == 8) ? g_s3s  : g_w3s + e * NOUT;
    } else {
        Bq1 = (e == 8) ? g_s2q1 : g_w2q1 + (size_t)e * NOUT * K;
        Bq2 = (e == 8) ? g_s2q2 : g_w2q2 + (size_t)e * NOUT * K;
        Bs  = (e == 8) ? g_s2s  : g_w2s + e * NOUT;
    }
    Aq1 = (MODE < 2) ? g_xq1 : g_hq1;
    Aq2 = (MODE < 2) ? g_xq2 : g_hq2;

    int tid = threadIdx.x;
    int lane = tid & 31, w = tid >> 5;
    int wm = w & 3, wn = w >> 2;
    int* rowtok = (int*)smem;
    float* sa_s = (float*)(smem + 512);
    float* sb_s = (float*)(smem + 1024);
    uint32_t sb = smem_u32(smem);

    if (MODE < 2 && tid < 128) {
        int r = m0 + tid;
        rowtok[tid] = (e == 8) ? r : ((r < cnt) ? g_rows[e * SEG + r] : g_rows[e * SEG]);
    }
    __syncthreads();
    if (tid < 128) {
        if (MODE < 2) {
            sa_s[tid] = g_xs[rowtok[tid]];
        } else {
            int rr = m0 + tid;
            if (rr >= cnt) rr = m0;
            sa_s[tid] = g_hs[e * SEG + rr];
        }
        sb_s[tid] = Bs[n0 + tid];
    }

    load_stage<MODE, K>(sb, 0, rowtok, e, cnt, m0, n0, Aq1, Aq2, Bq1, Bq2, 0, tid);
    CP_COMMIT();
    load_stage<MODE, K>(sb, 1, rowtok, e, cnt, m0, n0, Aq1, Aq2, Bq1, Bq2, 1, tid);
    CP_COMMIT();

    int accH[2][8][4], accM[2][8][4];
#pragma unroll
    for (int mt = 0; mt < 2; mt++)
#pragma unroll
        for (int nt = 0; nt < 8; nt++)
#pragma unroll
            for (int q = 0; q < 4; q++) { accH[mt][nt][q] = 0; accM[mt][nt][q] = 0; }

    for (int kc = 0; kc < NC; kc++) {
        if (kc + 2 < NC)
            load_stage<MODE, K>(sb, (kc + 2) % NSTAGE, rowtok, e, cnt, m0, n0,
                                Aq1, Aq2, Bq1, Bq2, kc + 2, tid);
        CP_COMMIT();
        CP_WAIT2();
        __syncthreads();
        compute_stage(smem + 2048 + (kc % NSTAGE) * STAGEB, accH, accM, lane, wm, wn);
        __syncthreads();
    }

    // ---- epilogue: scale by rank-1 (sa x sb), fuse activation ----
    int g = lane >> 2, tg = lane & 3;
#pragma unroll
    for (int mt = 0; mt < 2; mt++) {
#pragma unroll
        for (int rh = 0; rh < 2; rh++) {
            int row = wm * 32 + mt * 16 + g + rh * 8;
            int r = m0 + row;
            if (r >= cnt) continue;
            float sa = sa_s[row];
            size_t rb = ((size_t)e * SEG + r) * NOUT;
#pragma unroll
            for (int nt = 0; nt < 8; nt++) {
                int colL = wn * 64 + nt * 8 + tg * 2;
                int col = n0 + colL;
                float sc0 = sa * sb_s[colL];
                float sc1 = sa * sb_s[colL + 1];
                float d0 = sc0 * ((float)accH[mt][nt][rh * 2 + 0] +
                                  (float)accM[mt][nt][rh * 2 + 0] * 0.00390625f);
                float d1 = sc1 * ((float)accH[mt][nt][rh * 2 + 1] +
                                  (float)accM[mt][nt][rh * 2 + 1] * 0.00390625f);
                if (MODE == 0) {
                    *(float2*)(g_h1 + rb + col) = make_float2(d0, d1);
                } else if (MODE == 1) {
                    float2 h = *(const float2*)(g_h1 + rb + col);
                    float p0 = 0.5f * h.x * (1.f + erff(h.x * 0.70710678f)) * d0;
                    float p1 = 0.5f * h.y * (1.f + erff(h.y * 0.70710678f)) * d1;
                    *(float2*)(g_hp + rb + col) = make_float2(p0, p1);
                } else {
                    *(float2*)(g_orow + rb + col) = make_float2(d0, d1);
                }
            }
        }
    }
}

// ---------------- quantize h rows (row max + 2-limb split) ----------------
__global__ void k_quant_h() {
    __shared__ float red[8];
    __shared__ float s_max;
    int rowg = blockIdx.x;           // 0..NSEG*SEG-1
    int e = rowg >> 12;
    int r = rowg & (SEG - 1);
    int cnt = (e == 8) ? SEG : g_cnt[e];
    if (r >= cnt) return;
    int tid = threadIdx.x;
    const float* src = g_hp + (size_t)rowg * DFF;
    float m = 0.f;
    for (int i = tid; i < DFF; i += 256) m = fmaxf(m, fabsf(src[i]));
#pragma unroll
    for (int o = 16; o; o >>= 1) m = fmaxf(m, __shfl_xor_sync(0xffffffffu, m, o));
    if ((tid & 31) == 0) red[tid >> 5] = m;
    __syncthreads();
    if (tid == 0) {
        float mm = 0.f;
#pragma unroll
        for (int i = 0; i < 8; i++) mm = fmaxf(mm, red[i]);
        s_max = mm;
        g_hs[rowg] = mm * (1.f / 127.f);
    }
    __syncthreads();
    float mx = s_max;
    float s = mx * (1.f / 127.f);
    float inv1 = (mx > 0.f) ? 127.f / mx : 0.f;
    size_t base = (size_t)rowg * DFF;
    for (int i = tid; i < DFF; i += 256) {
        float a = src[i];
        float q1f = rintf(a * inv1);
        q1f = fminf(fmaxf(q1f, -127.f), 127.f);
        float rr = a - q1f * s;
        g_hq1[base + i] = (int8_t)(int)q1f;
        g_hq2[base + i] = q_clamp(rintf(rr * inv1 * 256.f));
    }
}

// ---------------- combine: out = x + shared + w0*row0 + w1*row1 ----------------
__global__ void k_combine(const float* __restrict__ x, float* __restrict__ out) {
    int t = blockIdx.x;
    int p0 = g_pos[t * 2 + 0], p1 = g_pos[t * 2 + 1];
    float w0 = g_rw[p0], w1 = g_rw[p1];
    const float* xr = x + (size_t)t * DM;
    const float* sh = g_orow + ((size_t)8 * SEG + t) * DM;
    const float* r0 = g_orow + (size_t)p0 * DM;
    const float* r1 = g_orow + (size_t)p1 * DM;
    float* o = out + (size_t)t * DM;
    for (int i = threadIdx.x; i < DM; i += blockDim.x)
        o[i] = xr[i] + sh[i] + w0 * r0[i] + w1 * r1[i];
}

// ---------------- launch ----------------
extern "C" void kernel_launch(void* const* d_in, const int* in_sizes, int n_in,
                              void* d_out, int out_size) {
    const float* x   = (const float*)d_in[0];
    const float* gw  = (const float*)d_in[1];
    const float* w1  = (const float*)d_in[2];
    const float* w2  = (const float*)d_in[3];
    const float* w3  = (const float*)d_in[4];
    const float* sw1 = (const float*)d_in[5];
    const float* sw2 = (const float*)d_in[6];
    const float* sw3 = (const float*)d_in[7];
    float* out = (float*)d_out;

    cudaFuncSetAttribute(k_gemm<0>, cudaFuncAttributeMaxDynamicSharedMemorySize, SMEM_TOTAL);
    cudaFuncSetAttribute(k_gemm<1>, cudaFuncAttributeMaxDynamicSharedMemorySize, SMEM_TOTAL);
    cudaFuncSetAttribute(k_gemm<2>, cudaFuncAttributeMaxDynamicSharedMemorySize, SMEM_TOTAL);

    k_prep<<<59904, 256>>>(w1, w2, w3, sw1, sw2, sw3);      // also resets g_cnt
    k_rms_gate<<<NTOK, 256>>>(x, gw);

    dim3 gup(DFF / 128, SEG / 128, NSEG);   // 22 x 32 x 9
    k_gemm<0><<<gup, 256, SMEM_TOTAL>>>();
    k_gemm<1><<<gup, 256, SMEM_TOTAL>>>();

    k_quant_h<<<NSEG * SEG, 256>>>();

    dim3 gdn(DM / 128, SEG / 128, NSEG);    // 8 x 32 x 9
    k_gemm<2><<<gdn, 256, SMEM_TOTAL>>>();

    k_combine<<<NTOK, 256>>>(x, out);
}

// round 11
// speedup vs baseline: 3.3365x; 3.3365x over previous
#include <cuda_runtime.h>
#include <cuda_fp16.h>
#include <math.h>
#include <stdint.h>

#define NTOK 4096
#define DM   1024
#define DFF  2816
#define NEXP 8
#define NSEG 9
#define SEG  4096

#define PLANE  10240          // 128 rows * 80 bytes (32 fp16 = 64B + 16B pad)
#define STAGEB (3 * PLANE)    // A, Bh, Bl
#define NSTAGE 3
#define SMEM_TOTAL (1024 + NSTAGE * STAGEB)   // 93184

// ---------------- scratch (device globals; allocation-free) ----------------
__device__ int      g_cnt[NEXP];
__device__ int      g_rows[NEXP * SEG];
__device__ float    g_rw[NSEG * SEG];
__device__ int      g_pos[NTOK * 2];
__device__ uint16_t g_xh[(size_t)NTOK * DM];          // fp16(x_norm)
// weights: two fp16 limbs each (hi + residual)
__device__ uint16_t g_w1h[(size_t)NEXP * DFF * DM];
__device__ uint16_t g_w1l[(size_t)NEXP * DFF * DM];
__device__ uint16_t g_w3h[(size_t)NEXP * DFF * DM];
__device__ uint16_t g_w3l[(size_t)NEXP * DFF * DM];
__device__ uint16_t g_w2h[(size_t)NEXP * DM * DFF];
__device__ uint16_t g_w2l[(size_t)NEXP * DM * DFF];
__device__ uint16_t g_s1h[(size_t)DFF * DM];
__device__ uint16_t g_s1l[(size_t)DFF * DM];
__device__ uint16_t g_s3h[(size_t)DFF * DM];
__device__ uint16_t g_s3l[(size_t)DFF * DM];
__device__ uint16_t g_s2h[(size_t)DM * DFF];
__device__ uint16_t g_s2l[(size_t)DM * DFF];
// intermediates
__device__ float    g_h1[(size_t)NSEG * SEG * DFF];   // up1 pre-activation fp32
__device__ uint16_t g_hh[(size_t)NSEG * SEG * DFF];   // fp16(gelu(h1)*h3)
__device__ float    g_orow[(size_t)NSEG * SEG * DM];  // down output rows

// ---------------- helpers ----------------
__device__ __forceinline__ uint32_t smem_u32(const void* p) {
    uint32_t a;
    asm("{ .reg .u64 t; cvta.to.shared.u64 t, %1; cvt.u32.u64 %0, t; }" : "=r"(a) : "l"(p));
    return a;
}
#define CP_ASYNC16(dst, src) \
    asm volatile("cp.async.cg.shared.global [%0], [%1], 16;" :: "r"(dst), "l"(src))
#define CP_COMMIT()  asm volatile("cp.async.commit_group;" ::: "memory")
#define CP_WAIT2()   asm volatile("cp.async.wait_group 2;" ::: "memory")

__device__ __forceinline__ void mma16816(float* d, const uint32_t* a, const uint32_t* b) {
    asm volatile(
        "mma.sync.aligned.m16n8k16.row.col.f32.f16.f16.f32 "
        "{%0,%1,%2,%3}, {%4,%5,%6,%7}, {%8,%9}, {%0,%1,%2,%3};"
        : "+f"(d[0]), "+f"(d[1]), "+f"(d[2]), "+f"(d[3])
        : "r"(a[0]), "r"(a[1]), "r"(a[2]), "r"(a[3]), "r"(b[0]), "r"(b[1]));
}
__device__ __forceinline__ uint16_t f2h(float x) {
    return __half_as_ushort(__float2half_rn(x));
}

// ---------------- prep: reset counters + split all 6 weight tensors (fp16 hi/lo) ----------------
__global__ void k_prep(const float* __restrict__ w1, const float* __restrict__ w2,
                       const float* __restrict__ w3, const float* __restrict__ s1,
                       const float* __restrict__ s2, const float* __restrict__ s3) {
    const int nW = NEXP * DFF * DM;
    const int nS = DFF * DM;
    int y = blockIdx.y;
    if (y == 0 && blockIdx.x == 0 && threadIdx.x < NEXP) g_cnt[threadIdx.x] = 0;

    const float* src;
    uint16_t *hi, *lo;
    int n;
    if (y == 0)      { src = w1; hi = g_w1h; lo = g_w1l; n = nW; }
    else if (y == 1) { src = w3; hi = g_w3h; lo = g_w3l; n = nW; }
    else if (y == 2) { src = w2; hi = g_w2h; lo = g_w2l; n = nW; }
    else if (y == 3) { src = s1; hi = g_s1h; lo = g_s1l; n = nS; }
    else if (y == 4) { src = s3; hi = g_s3h; lo = g_s3l; n = nS; }
    else             { src = s2; hi = g_s2h; lo = g_s2l; n = nS; }

    int i4 = (blockIdx.x * 256 + threadIdx.x) * 4;
    if (i4 >= n) return;
    float4 v = *(const float4*)(src + i4);
    __half h0 = __float2half_rn(v.x), h1 = __float2half_rn(v.y);
    __half h2 = __float2half_rn(v.z), h3 = __float2half_rn(v.w);
    ushort4 hv = make_ushort4(__half_as_ushort(h0), __half_as_ushort(h1),
                              __half_as_ushort(h2), __half_as_ushort(h3));
    ushort4 lv = make_ushort4(f2h(v.x - __half2float(h0)), f2h(v.y - __half2float(h1)),
                              f2h(v.z - __half2float(h2)), f2h(v.w - __half2float(h3)));
    *(ushort4*)(hi + i4) = hv;
    *(ushort4*)(lo + i4) = lv;
}

// ---------------- RMSNorm + gating + routing (writes fp16 x_norm) ----------------
__global__ void k_rms_gate(const float* __restrict__ x, const float* __restrict__ gw) {
    __shared__ float xs[DM];
    __shared__ float red[8];
    __shared__ float logits[NEXP];
    __shared__ float s_scale;

    int t = blockIdx.x, tid = threadIdx.x;
    const float* xr = x + (size_t)t * DM;

    float v[4];
    float ss = 0.f;
#pragma unroll
    for (int i = 0; i < 4; i++) { v[i] = xr[tid + 256 * i]; ss += v[i] * v[i]; }
#pragma unroll
    for (int o = 16; o; o >>= 1) ss += __shfl_xor_sync(0xffffffffu, ss, o);
    if ((tid & 31) == 0) red[tid >> 5] = ss;
    __syncthreads();
    if (tid == 0) {
        float s = 0.f;
#pragma unroll
        for (int i = 0; i < 8; i++) s += red[i];
        s_scale = rsqrtf(s / (float)DM + 1e-6f);
    }
    __syncthreads();
    float sc = s_scale;
#pragma unroll
    for (int i = 0; i < 4; i++) {
        float y = v[i] * sc;
        xs[tid + 256 * i] = y;
        g_xh[(size_t)t * DM + tid + 256 * i] = f2h(y);
    }
    __syncthreads();

    int w = tid >> 5, lane = tid & 31;
    const float* ge = gw + w * DM;
    float acc = 0.f;
    for (int i = lane; i < DM; i += 32) acc += xs[i] * ge[i];
#pragma unroll
    for (int o = 16; o; o >>= 1) acc += __shfl_xor_sync(0xffffffffu, acc, o);
    if (lane == 0) logits[w] = acc;
    __syncthreads();

    if (tid == 0) {
        int b0 = 0; float l0 = logits[0];
        for (int e = 1; e < NEXP; e++) if (logits[e] > l0) { l0 = logits[e]; b0 = e; }
        int b1 = -1; float l1 = -1e30f;
        for (int e = 0; e < NEXP; e++) if (e != b0 && logits[e] > l1) { l1 = logits[e]; b1 = e; }
        float w0 = 1.f / (1.f + expf(l1 - l0));
        float w1v = 1.f - w0;
        int s0 = atomicAdd(&g_cnt[b0], 1);
        g_rows[b0 * SEG + s0] = t; g_rw[b0 * SEG + s0] = w0;  g_pos[t * 2 + 0] = b0 * SEG + s0;
        int s1 = atomicAdd(&g_cnt[b1], 1);
        g_rows[b1 * SEG + s1] = t; g_rw[b1 * SEG + s1] = w1v; g_pos[t * 2 + 1] = b1 * SEG + s1;
    }
}

// ---------------- stage loader: cp.async of 3 fp16 planes (A, Bh, Bl) ----------------
// Each plane: 128 rows x 32 fp16 (64B data + 16B pad = 80B stride).
template <int MODE, int K>
__device__ __forceinline__ void load_stage(uint32_t sbase, int stg, const int* rowtok,
                                           int e, int cnt, int m0, int n0,
                                           const uint16_t* A,
                                           const uint16_t* Bh, const uint16_t* Bl,
                                           int kc, int tid) {
    uint32_t stbase = sbase + 1024 + stg * STAGEB;
#pragma unroll
    for (int c = 0; c < 6; c++) {
        int i = tid + c * 256;        // 0..1535
        int plane = i >> 9;
        int j = i & 511;
        int row = j >> 2;
        int kq = (j & 3) * 8;         // fp16 elements (16B chunks)
        const uint16_t* src;
        if (plane == 0) {
            size_t r;
            if (MODE < 2) {
                r = (size_t)rowtok[row];
            } else {
                int rr = m0 + row;
                if (rr >= cnt) rr = m0;
                r = (size_t)e * SEG + rr;
            }
            src = A + r * K + kc * 32 + kq;
        } else {
            const uint16_t* P = (plane == 1) ? Bh : Bl;
            src = P + (size_t)(n0 + row) * K + kc * 32 + kq;
        }
        uint32_t dst = stbase + plane * PLANE + row * 80 + (j & 3) * 16;
        CP_ASYNC16(dst, src);
    }
}

// ---------------- per-stage compute: 2 x k16 steps, 2-term weight-limb split ----------------
__device__ __forceinline__ void compute_stage(const char* st, float acc[2][8][4],
                                              int lane, int wm, int wn) {
    int g = lane >> 2, tg = lane & 3;
    const char* Ap  = st;
    const char* Bhp = st + PLANE;
    const char* Blp = st + 2 * PLANE;
#pragma unroll
    for (int kk = 0; kk < 2; kk++) {
        int c0 = (kk * 16 + tg * 2) * 2;   // byte offset within row
        uint32_t ah[2][4];
#pragma unroll
        for (int mt = 0; mt < 2; mt++) {
            int rb = wm * 32 + mt * 16;
            ah[mt][0] = *(const uint32_t*)(Ap + (rb + g) * 80 + c0);
            ah[mt][1] = *(const uint32_t*)(Ap + (rb + g + 8) * 80 + c0);
            ah[mt][2] = *(const uint32_t*)(Ap + (rb + g) * 80 + c0 + 16);
            ah[mt][3] = *(const uint32_t*)(Ap + (rb + g + 8) * 80 + c0 + 16);
        }
        uint32_t bh[8][2], bl[8][2];
#pragma unroll
        for (int nt = 0; nt < 8; nt++) {
            int nr = wn * 64 + nt * 8 + g;
            bh[nt][0] = *(const uint32_t*)(Bhp + nr * 80 + c0);
            bh[nt][1] = *(const uint32_t*)(Bhp + nr * 80 + c0 + 16);
            bl[nt][0] = *(const uint32_t*)(Blp + nr * 80 + c0);
            bl[nt][1] = *(const uint32_t*)(Blp + nr * 80 + c0 + 16);
        }
#pragma unroll
        for (int mt = 0; mt < 2; mt++)
#pragma unroll
            for (int nt = 0; nt < 8; nt++) {
                mma16816(acc[mt][nt], ah[mt], bh[nt]);
                mma16816(acc[mt][nt], ah[mt], bl[nt]);
            }
    }
}

// ---------------- HMMA GEMM, 3-stage cp.async pipeline ----------------
// MODE 0: up1 (A = gathered fp16 x_norm, B = w1 limbs) -> g_h1 fp32
// MODE 1: up3 (A = gathered fp16 x_norm, B = w3 limbs) -> epi: fp16(gelu(g_h1)*d) -> g_hh
// MODE 2: down (A = g_hh,               B = w2 limbs) -> g_orow fp32
template <int MODE>
__global__ __launch_bounds__(256)
void k_gemm() {
    constexpr int K    = (MODE < 2) ? DM : DFF;
    constexpr int NOUT = (MODE < 2) ? DFF : DM;
    constexpr int NC   = K / 32;

    extern __shared__ char smem[];
    int e = blockIdx.z;
    int cnt = (e == 8) ? SEG : g_cnt[e];
    int m0 = blockIdx.y * 128;
    if (m0 >= cnt) return;
    int n0 = blockIdx.x * 128;

    const uint16_t *A, *Bh, *Bl;
    if (MODE == 0) {
        Bh = (e == 8) ? g_s1h : g_w1h + (size_t)e * NOUT * K;
        Bl = (e == 8) ? g_s1l : g_w1l + (size_t)e * NOUT * K;
    } else if (MODE == 1) {
        Bh = (e == 8) ? g_s3h : g_w3h + (size_t)e * NOUT * K;
        Bl = (e == 8) ? g_s3l : g_w3l + (size_t)e * NOUT * K;
    } else {
        Bh = (e == 8) ? g_s2h : g_w2h + (size_t)e * NOUT * K;
        Bl = (e == 8) ? g_s2l : g_w2l + (size_t)e * NOUT * K;
    }
    A = (MODE < 2) ? g_xh : g_hh;

    int tid = threadIdx.x;
    int lane = tid & 31, w = tid >> 5;
    int wm = w & 3, wn = w >> 2;
    int* rowtok = (int*)smem;
    uint32_t sb = smem_u32(smem);

    if (MODE < 2 && tid < 128) {
        int r = m0 + tid;
        rowtok[tid] = (e == 8) ? r : ((r < cnt) ? g_rows[e * SEG + r] : g_rows[e * SEG]);
    }
    __syncthreads();

    load_stage<MODE, K>(sb, 0, rowtok, e, cnt, m0, n0, A, Bh, Bl, 0, tid);
    CP_COMMIT();
    load_stage<MODE, K>(sb, 1, rowtok, e, cnt, m0, n0, A, Bh, Bl, 1, tid);
    CP_COMMIT();

    float acc[2][8][4];
#pragma unroll
    for (int mt = 0; mt < 2; mt++)
#pragma unroll
        for (int nt = 0; nt < 8; nt++)
#pragma unroll
            for (int q = 0; q < 4; q++) acc[mt][nt][q] = 0.f;

    for (int kc = 0; kc < NC; kc++) {
        if (kc + 2 < NC)
            load_stage<MODE, K>(sb, (kc + 2) % NSTAGE, rowtok, e, cnt, m0, n0,
                                A, Bh, Bl, kc + 2, tid);
        CP_COMMIT();
        CP_WAIT2();
        __syncthreads();
        compute_stage(smem + 1024 + (kc % NSTAGE) * STAGEB, acc, lane, wm, wn);
        __syncthreads();
    }

    // ---- epilogue ----
    int g = lane >> 2, tg = lane & 3;
#pragma unroll
    for (int mt = 0; mt < 2; mt++) {
#pragma unroll
        for (int rh = 0; rh < 2; rh++) {
            int row = wm * 32 + mt * 16 + g + rh * 8;
            int r = m0 + row;
            if (r >= cnt) continue;
            size_t rb = ((size_t)e * SEG + r) * NOUT;
#pragma unroll
            for (int nt = 0; nt < 8; nt++) {
                int col = n0 + wn * 64 + nt * 8 + tg * 2;
                float d0 = acc[mt][nt][rh * 2 + 0];
                float d1 = acc[mt][nt][rh * 2 + 1];
                if (MODE == 0) {
                    *(float2*)(g_h1 + rb + col) = make_float2(d0, d1);
                } else if (MODE == 1) {
                    float2 h = *(const float2*)(g_h1 + rb + col);
                    float p0 = 0.5f * h.x * (1.f + erff(h.x * 0.70710678f)) * d0;
                    float p1 = 0.5f * h.y * (1.f + erff(h.y * 0.70710678f)) * d1;
                    uint32_t pk = (uint32_t)f2h(p0) | ((uint32_t)f2h(p1) << 16);
                    *(uint32_t*)(g_hh + rb + col) = pk;
                } else {
                    *(float2*)(g_orow + rb + col) = make_float2(d0, d1);
                }
            }
        }
    }
}

// ---------------- combine: out = x + shared + w0*row0 + w1*row1 ----------------
__global__ void k_combine(const float* __restrict__ x, float* __restrict__ out) {
    int t = blockIdx.x;
    int p0 = g_pos[t * 2 + 0], p1 = g_pos[t * 2 + 1];
    float w0 = g_rw[p0], w1 = g_rw[p1];
    const float* xr = x + (size_t)t * DM;
    const float* sh = g_orow + ((size_t)8 * SEG + t) * DM;
    const float* r0 = g_orow + (size_t)p0 * DM;
    const float* r1 = g_orow + (size_t)p1 * DM;
    float* o = out + (size_t)t * DM;
    for (int i = threadIdx.x; i < DM; i += blockDim.x)
        o[i] = xr[i] + sh[i] + w0 * r0[i] + w1 * r1[i];
}

// ---------------- launch ----------------
extern "C" void kernel_launch(void* const* d_in, const int* in_sizes, int n_in,
                              void* d_out, int out_size) {
    const float* x   = (const float*)d_in[0];
    const float* gw  = (const float*)d_in[1];
    const float* w1  = (const float*)d_in[2];
    const float* w2  = (const float*)d_in[3];
    const float* w3  = (const float*)d_in[4];
    const float* sw1 = (const float*)d_in[5];
    const float* sw2 = (const float*)d_in[6];
    const float* sw3 = (const float*)d_in[7];
    float* out = (float*)d_out;

    cudaFuncSetAttribute(k_gemm<0>, cudaFuncAttributeMaxDynamicSharedMemorySize, SMEM_TOTAL);
    cudaFuncSetAttribute(k_gemm<1>, cudaFuncAttributeMaxDynamicSharedMemorySize, SMEM_TOTAL);
    cudaFuncSetAttribute(k_gemm<2>, cudaFuncAttributeMaxDynamicSharedMemorySize, SMEM_TOTAL);

    const int nW = NEXP * DFF * DM;         // 23,068,672
    dim3 gprep(nW / 1024, 6);               // big tensors sized; small ones early-exit
    k_prep<<<gprep, 256>>>(w1, w2, w3, sw1, sw2, sw3);   // also resets g_cnt

    k_rms_gate<<<NTOK, 256>>>(x, gw);

    dim3 gup(DFF / 128, SEG / 128, NSEG);   // 22 x 32 x 9
    k_gemm<0><<<gup, 256, SMEM_TOTAL>>>();
    k_gemm<1><<<gup, 256, SMEM_TOTAL>>>();

    dim3 gdn(DM / 128, SEG / 128, NSEG);    // 8 x 32 x 9
    k_gemm<2><<<gdn, 256, SMEM_TOTAL>>>();

    k_combine<<<NTOK, 256>>>(x, out);
}

// round 16
// speedup vs baseline: 3.5012x; 1.0494x over previous
#include <cuda_runtime.h>
#include <cuda_fp16.h>
#include <math.h>
#include <stdint.h>

#define NTOK 4096
#define DM   1024
#define DFF  2816
#define NEXP 8
#define NSEG 9
#define SEG  4096

#define PLANE  10240          // 128 rows * 80 bytes (32 fp16 = 64B + 16B pad)
#define STAGEB (3 * PLANE)    // A, Bh, Bl
#define NSTAGE 3
#define SMEM_TOTAL (1024 + NSTAGE * STAGEB)   // 93184

// ---------------- scratch (device globals; allocation-free) ----------------
__device__ int      g_cnt[NEXP];
__device__ int      g_rows[NEXP * SEG];
__device__ float    g_rw[NSEG * SEG];
__device__ int      g_pos[NTOK * 2];
__device__ uint16_t g_xh[(size_t)NTOK * DM];          // fp16(x_norm)
// weights: two fp16 limbs each (hi + residual)
__device__ uint16_t g_w1h[(size_t)NEXP * DFF * DM];
__device__ uint16_t g_w1l[(size_t)NEXP * DFF * DM];
__device__ uint16_t g_w3h[(size_t)NEXP * DFF * DM];
__device__ uint16_t g_w3l[(size_t)NEXP * DFF * DM];
__device__ uint16_t g_w2h[(size_t)NEXP * DM * DFF];
__device__ uint16_t g_w2l[(size_t)NEXP * DM * DFF];
__device__ uint16_t g_s1h[(size_t)DFF * DM];
__device__ uint16_t g_s1l[(size_t)DFF * DM];
__device__ uint16_t g_s3h[(size_t)DFF * DM];
__device__ uint16_t g_s3l[(size_t)DFF * DM];
__device__ uint16_t g_s2h[(size_t)DM * DFF];
__device__ uint16_t g_s2l[(size_t)DM * DFF];
// intermediates
__device__ float    g_h1[(size_t)NSEG * SEG * DFF];   // up1 pre-activation fp32
__device__ uint16_t g_hh[(size_t)NSEG * SEG * DFF];   // fp16(gelu(h1)*h3)
__device__ float    g_orow[(size_t)NSEG * SEG * DM];  // down output rows

// ---------------- helpers ----------------
__device__ __forceinline__ uint32_t smem_u32(const void* p) {
    uint32_t a;
    asm("{ .reg .u64 t; cvta.to.shared.u64 t, %1; cvt.u32.u64 %0, t; }" : "=r"(a) : "l"(p));
    return a;
}
#define CP_ASYNC16(dst, src) \
    asm volatile("cp.async.cg.shared.global [%0], [%1], 16;" :: "r"(dst), "l"(src))
#define CP_COMMIT()  asm volatile("cp.async.commit_group;" ::: "memory")
#define CP_WAIT1()   asm volatile("cp.async.wait_group 1;" ::: "memory")

__device__ __forceinline__ void mma16816(float* d, const uint32_t* a, const uint32_t* b) {
    asm volatile(
        "mma.sync.aligned.m16n8k16.row.col.f32.f16.f16.f32 "
        "{%0,%1,%2,%3}, {%4,%5,%6,%7}, {%8,%9}, {%0,%1,%2,%3};"
        : "+f"(d[0]), "+f"(d[1]), "+f"(d[2]), "+f"(d[3])
        : "r"(a[0]), "r"(a[1]), "r"(a[2]), "r"(a[3]), "r"(b[0]), "r"(b[1]));
}
__device__ __forceinline__ uint16_t f2h(float x) {
    return __half_as_ushort(__float2half_rn(x));
}

// ---------------- prep: reset counters + split all 6 weight tensors (fp16 hi/lo) ----------------
__global__ void k_prep(const float* __restrict__ w1, const float* __restrict__ w2,
                       const float* __restrict__ w3, const float* __restrict__ s1,
                       const float* __restrict__ s2, const float* __restrict__ s3) {
    const int nW = NEXP * DFF * DM;
    const int nS = DFF * DM;
    int y = blockIdx.y;
    if (y == 0 && blockIdx.x == 0 && threadIdx.x < NEXP) g_cnt[threadIdx.x] = 0;

    const float* src;
    uint16_t *hi, *lo;
    int n;
    if (y == 0)      { src = w1; hi = g_w1h; lo = g_w1l; n = nW; }
    else if (y == 1) { src = w3; hi = g_w3h; lo = g_w3l; n = nW; }
    else if (y == 2) { src = w2; hi = g_w2h; lo = g_w2l; n = nW; }
    else if (y == 3) { src = s1; hi = g_s1h; lo = g_s1l; n = nS; }
    else if (y == 4) { src = s3; hi = g_s3h; lo = g_s3l; n = nS; }
    else             { src = s2; hi = g_s2h; lo = g_s2l; n = nS; }

    int i4 = (blockIdx.x * 256 + threadIdx.x) * 4;
    if (i4 >= n) return;
    float4 v = *(const float4*)(src + i4);
    __half h0 = __float2half_rn(v.x), h1 = __float2half_rn(v.y);
    __half h2 = __float2half_rn(v.z), h3 = __float2half_rn(v.w);
    ushort4 hv = make_ushort4(__half_as_ushort(h0), __half_as_ushort(h1),
                              __half_as_ushort(h2), __half_as_ushort(h3));
    ushort4 lv = make_ushort4(f2h(v.x - __half2float(h0)), f2h(v.y - __half2float(h1)),
                              f2h(v.z - __half2float(h2)), f2h(v.w - __half2float(h3)));
    *(ushort4*)(hi + i4) = hv;
    *(ushort4*)(lo + i4) = lv;
}

// ---------------- RMSNorm + gating + routing (writes fp16 x_norm) ----------------
__global__ void k_rms_gate(const float* __restrict__ x, const float* __restrict__ gw) {
    __shared__ float xs[DM];
    __shared__ float red[8];
    __shared__ float logits[NEXP];
    __shared__ float s_scale;

    int t = blockIdx.x, tid = threadIdx.x;
    const float* xr = x + (size_t)t * DM;

    float v[4];
    float ss = 0.f;
#pragma unroll
    for (int i = 0; i < 4; i++) { v[i] = xr[tid + 256 * i]; ss += v[i] * v[i]; }
#pragma unroll
    for (int o = 16; o; o >>= 1) ss += __shfl_xor_sync(0xffffffffu, ss, o);
    if ((tid & 31) == 0) red[tid >> 5] = ss;
    __syncthreads();
    if (tid == 0) {
        float s = 0.f;
#pragma unroll
        for (int i = 0; i < 8; i++) s += red[i];
        s_scale = rsqrtf(s / (float)DM + 1e-6f);
    }
    __syncthreads();
    float sc = s_scale;
#pragma unroll
    for (int i = 0; i < 4; i++) {
        float y = v[i] * sc;
        xs[tid + 256 * i] = y;
        g_xh[(size_t)t * DM + tid + 256 * i] = f2h(y);
    }
    __syncthreads();

    int w = tid >> 5, lane = tid & 31;
    const float* ge = gw + w * DM;
    float acc = 0.f;
    for (int i = lane; i < DM; i += 32) acc += xs[i] * ge[i];
#pragma unroll
    for (int o = 16; o; o >>= 1) acc += __shfl_xor_sync(0xffffffffu, acc, o);
    if (lane == 0) logits[w] = acc;
    __syncthreads();

    if (tid == 0) {
        int b0 = 0; float l0 = logits[0];
        for (int e = 1; e < NEXP; e++) if (logits[e] > l0) { l0 = logits[e]; b0 = e; }
        int b1 = -1; float l1 = -1e30f;
        for (int e = 0; e < NEXP; e++) if (e != b0 && logits[e] > l1) { l1 = logits[e]; b1 = e; }
        float w0 = 1.f / (1.f + expf(l1 - l0));
        float w1v = 1.f - w0;
        int s0 = atomicAdd(&g_cnt[b0], 1);
        g_rows[b0 * SEG + s0] = t; g_rw[b0 * SEG + s0] = w0;  g_pos[t * 2 + 0] = b0 * SEG + s0;
        int s1 = atomicAdd(&g_cnt[b1], 1);
        g_rows[b1 * SEG + s1] = t; g_rw[b1 * SEG + s1] = w1v; g_pos[t * 2 + 1] = b1 * SEG + s1;
    }
}

// ---------------- stage loader: cp.async of 3 fp16 planes (A, Bh, Bl) ----------------
// Each plane: 128 rows x 32 fp16 (64B data + 16B pad = 80B stride).
template <int MODE, int K>
__device__ __forceinline__ void load_stage(uint32_t sbase, int stg, const int* rowtok,
                                           int e, int cnt, int m0, int n0,
                                           const uint16_t* A,
                                           const uint16_t* Bh, const uint16_t* Bl,
                                           int kc, int tid) {
    uint32_t stbase = sbase + 1024 + stg * STAGEB;
#pragma unroll
    for (int c = 0; c < 6; c++) {
        int i = tid + c * 256;        // 0..1535
        int plane = i >> 9;
        int j = i & 511;
        int row = j >> 2;
        int kq = (j & 3) * 8;         // fp16 elements (16B chunks)
        const uint16_t* src;
        if (plane == 0) {
            size_t r;
            if (MODE < 2) {
                r = (size_t)rowtok[row];
            } else {
                int rr = m0 + row;
                if (rr >= cnt) rr = m0;
                r = (size_t)e * SEG + rr;
            }
            src = A + r * K + kc * 32 + kq;
        } else {
            const uint16_t* P = (plane == 1) ? Bh : Bl;
            src = P + (size_t)(n0 + row) * K + kc * 32 + kq;
        }
        uint32_t dst = stbase + plane * PLANE + row * 80 + (j & 3) * 16;
        CP_ASYNC16(dst, src);
    }
}

// ---------------- per-stage compute: 64x32 warp tile (mt=4, nt=4), 2-limb split ----------------
__device__ __forceinline__ void compute_stage(const char* st, float acc[4][4][4],
                                              int lane, int wm, int wn) {
    int g = lane >> 2, tg = lane & 3;
    const char* Ap  = st;
    const char* Bhp = st + PLANE;
    const char* Blp = st + 2 * PLANE;
#pragma unroll
    for (int kk = 0; kk < 2; kk++) {
        int c0 = (kk * 16 + tg * 2) * 2;   // byte offset within row
        uint32_t ah[4][4];
#pragma unroll
        for (int mt = 0; mt < 4; mt++) {
            int rb = wm * 64 + mt * 16;
            ah[mt][0] = *(const uint32_t*)(Ap + (rb + g) * 80 + c0);
            ah[mt][1] = *(const uint32_t*)(Ap + (rb + g + 8) * 80 + c0);
            ah[mt][2] = *(const uint32_t*)(Ap + (rb + g) * 80 + c0 + 16);
            ah[mt][3] = *(const uint32_t*)(Ap + (rb + g + 8) * 80 + c0 + 16);
        }
        uint32_t bh[4][2], bl[4][2];
#pragma unroll
        for (int nt = 0; nt < 4; nt++) {
            int nr = wn * 32 + nt * 8 + g;
            bh[nt][0] = *(const uint32_t*)(Bhp + nr * 80 + c0);
            bh[nt][1] = *(const uint32_t*)(Bhp + nr * 80 + c0 + 16);
            bl[nt][0] = *(const uint32_t*)(Blp + nr * 80 + c0);
            bl[nt][1] = *(const uint32_t*)(Blp + nr * 80 + c0 + 16);
        }
#pragma unroll
        for (int mt = 0; mt < 4; mt++)
#pragma unroll
            for (int nt = 0; nt < 4; nt++) {
                mma16816(acc[mt][nt], ah[mt], bh[nt]);
                mma16816(acc[mt][nt], ah[mt], bl[nt]);
            }
    }
}

// ---------------- HMMA GEMM, 3-stage cp.async pipeline, one barrier per k-chunk ----------------
// Tail-safe: CP_COMMIT every iteration (empty groups near the end keep
// wait_group 1 draining stage kc even when no new loads are issued).
// MODE 0: up1 (A = gathered fp16 x_norm, B = w1 limbs) -> g_h1 fp32
// MODE 1: up3 (A = gathered fp16 x_norm, B = w3 limbs) -> epi: fp16(gelu(g_h1)*d) -> g_hh
// MODE 2: down (A = g_hh,               B = w2 limbs) -> g_orow fp32
template <int MODE>
__global__ __launch_bounds__(256)
void k_gemm() {
    constexpr int K    = (MODE < 2) ? DM : DFF;
    constexpr int NOUT = (MODE < 2) ? DFF : DM;
    constexpr int NC   = K / 32;

    extern __shared__ char smem[];
    int e = blockIdx.z;
    int cnt = (e == 8) ? SEG : g_cnt[e];
    int m0 = blockIdx.y * 128;
    if (m0 >= cnt) return;
    int n0 = blockIdx.x * 128;

    const uint16_t *A, *Bh, *Bl;
    if (MODE == 0) {
        Bh = (e == 8) ? g_s1h : g_w1h + (size_t)e * NOUT * K;
        Bl = (e == 8) ? g_s1l : g_w1l + (size_t)e * NOUT * K;
    } else if (MODE == 1) {
        Bh = (e == 8) ? g_s3h : g_w3h + (size_t)e * NOUT * K;
        Bl = (e == 8) ? g_s3l : g_w3l + (size_t)e * NOUT * K;
    } else {
        Bh = (e == 8) ? g_s2h : g_w2h + (size_t)e * NOUT * K;
        Bl = (e == 8) ? g_s2l : g_w2l + (size_t)e * NOUT * K;
    }
    A = (MODE < 2) ? g_xh : g_hh;

    int tid = threadIdx.x;
    int lane = tid & 31, w = tid >> 5;
    int wm = w & 1, wn = w >> 1;       // 2 x 4 warp grid, each 64x32
    int* rowtok = (int*)smem;
    uint32_t sb = smem_u32(smem);

    if (MODE < 2 && tid < 128) {
        int r = m0 + tid;
        rowtok[tid] = (e == 8) ? r : ((r < cnt) ? g_rows[e * SEG + r] : g_rows[e * SEG]);
    }
    __syncthreads();

    load_stage<MODE, K>(sb, 0, rowtok, e, cnt, m0, n0, A, Bh, Bl, 0, tid);
    CP_COMMIT();
    load_stage<MODE, K>(sb, 1, rowtok, e, cnt, m0, n0, A, Bh, Bl, 1, tid);
    CP_COMMIT();

    float acc[4][4][4];
#pragma unroll
    for (int mt = 0; mt < 4; mt++)
#pragma unroll
        for (int nt = 0; nt < 4; nt++)
#pragma unroll
            for (int q = 0; q < 4; q++) acc[mt][nt][q] = 0.f;

    for (int kc = 0; kc < NC; kc++) {
        CP_WAIT1();              // >=2 groups always ahead of compute -> stage kc drained
        __syncthreads();         // stage-kc data visible to all; compute(kc-1) done by all
        if (kc + 2 < NC)
            load_stage<MODE, K>(sb, (kc + 2) % NSTAGE, rowtok, e, cnt, m0, n0,
                                A, Bh, Bl, kc + 2, tid);
        CP_COMMIT();             // unconditional: empty tail groups keep the wait honest
        compute_stage(smem + 1024 + (kc % NSTAGE) * STAGEB, acc, lane, wm, wn);
    }

    // ---- epilogue ----
    int g = lane >> 2, tg = lane & 3;
#pragma unroll
    for (int mt = 0; mt < 4; mt++) {
#pragma unroll
        for (int rh = 0; rh < 2; rh++) {
            int row = wm * 64 + mt * 16 + g + rh * 8;
            int r = m0 + row;
            if (r >= cnt) continue;
            size_t rb = ((size_t)e * SEG + r) * NOUT;
#pragma unroll
            for (int nt = 0; nt < 4; nt++) {
                int col = n0 + wn * 32 + nt * 8 + tg * 2;
                float d0 = acc[mt][nt][rh * 2 + 0];
                float d1 = acc[mt][nt][rh * 2 + 1];
                if (MODE == 0) {
                    *(float2*)(g_h1 + rb + col) = make_float2(d0, d1);
                } else if (MODE == 1) {
                    float2 h = *(const float2*)(g_h1 + rb + col);
                    float p0 = 0.5f * h.x * (1.f + erff(h.x * 0.70710678f)) * d0;
                    float p1 = 0.5f * h.y * (1.f + erff(h.y * 0.70710678f)) * d1;
                    uint32_t pk = (uint32_t)f2h(p0) | ((uint32_t)f2h(p1) << 16);
                    *(uint32_t*)(g_hh + rb + col) = pk;
                } else {
                    *(float2*)(g_orow + rb + col) = make_float2(d0, d1);
                }
            }
        }
    }
}

// ---------------- combine: out = x + shared + w0*row0 + w1*row1 ----------------
__global__ void k_combine(const float* __restrict__ x, float* __restrict__ out) {
    int t = blockIdx.x;
    int p0 = g_pos[t * 2 + 0], p1 = g_pos[t * 2 + 1];
    float w0 = g_rw[p0], w1 = g_rw[p1];
    const float* xr = x + (size_t)t * DM;
    const float* sh = g_orow + ((size_t)8 * SEG + t) * DM;
    const float* r0 = g_orow + (size_t)p0 * DM;
    const float* r1 = g_orow + (size_t)p1 * DM;
    float* o = out + (size_t)t * DM;
    for (int i = threadIdx.x; i < DM; i += blockDim.x)
        o[i] = xr[i] + sh[i] + w0 * r0[i] + w1 * r1[i];
}

// ---------------- launch ----------------
extern "C" void kernel_launch(void* const* d_in, const int* in_sizes, int n_in,
                              void* d_out, int out_size) {
    const float* x   = (const float*)d_in[0];
    const float* gw  = (const float*)d_in[1];
    const float* w1  = (const float*)d_in[2];
    const float* w2  = (const float*)d_in[3];
    const float* w3  = (const float*)d_in[4];
    const float* sw1 = (const float*)d_in[5];
    const float* sw2 = (const float*)d_in[6];
    const float* sw3 = (const float*)d_in[7];
    float* out = (float*)d_out;

    cudaFuncSetAttribute(k_gemm<0>, cudaFuncAttributeMaxDynamicSharedMemorySize, SMEM_TOTAL);
    cudaFuncSetAttribute(k_gemm<1>, cudaFuncAttributeMaxDynamicSharedMemorySize, SMEM_TOTAL);
    cudaFuncSetAttribute(k_gemm<2>, cudaFuncAttributeMaxDynamicSharedMemorySize, SMEM_TOTAL);

    const int nW = NEXP * DFF * DM;         // 23,068,672
    dim3 gprep(nW / 1024, 6);               // big tensors sized; small ones early-exit
    k_prep<<<gprep, 256>>>(w1, w2, w3, sw1, sw2, sw3);   // also resets g_cnt

    k_rms_gate<<<NTOK, 256>>>(x, gw);

    dim3 gup(DFF / 128, SEG / 128, NSEG);   // 22 x 32 x 9
    k_gemm<0><<<gup, 256, SMEM_TOTAL>>>();
    k_gemm<1><<<gup, 256, SMEM_TOTAL>>>();

    dim3 gdn(DM / 128, SEG / 128, NSEG);    // 8 x 32 x 9
    k_gemm<2><<<gdn, 256, SMEM_TOTAL>>>();

    k_combine<<<NTOK, 256>>>(x, out);
}